// round 11
// baseline (speedup 1.0000x reference)
#include <cuda_runtime.h>
#include <cstdint>

// Problem constants
constexpr int B  = 8;
constexpr int C  = 19;
constexpr int H  = 320;
constexpr int W  = 2048;
constexpr int HH_OFF = 10;
constexpr int HH_N  = 10;
constexpr int WW   = 128;
constexpr int P    = HH_N * WW;      // 1280
constexpr long long NE = (long long)B * P * P;

constexpr int WCHUNK = 256;
constexpr int NWCH   = W / WCHUNK;       // 8
constexpr int POOL_PER_B = HH_N * NWCH;  // 80
constexpr int POOL_BLOCKS = B * POOL_PER_B;   // 640
constexpr int RWARPS = 8;
constexpr int ATTN_PER_B = P / RWARPS;   // 160
constexpr int ATTN_BLOCKS = B * ATTN_PER_B;   // 1280
constexpr int CH = P / 4 / 32;           // 10

constexpr int ROW_BYTES   = P * 4;
constexpr int SLICE_BYTES = RWARPS * ROW_BYTES;  // 40960
constexpr int SLICE_LINES = SLICE_BYTES / 128;   // 320

__device__ int g_lab[B * P];
__device__ int g_done[B];
__device__ int g_cons[B];

__device__ __forceinline__ int ld_relaxed_gpu(const int* p) {
    int v;
    asm volatile("ld.global.relaxed.gpu.b32 %0, [%1];" : "=r"(v) : "l"(p));
    return v;
}

__device__ __forceinline__ void prefetch_l2(const void* p) {
    asm volatile("prefetch.global.L2 [%0];" :: "l"(p));
}

__device__ __forceinline__ float edit1(float en, bool same) {
    return same ? (en < 0.f ? 0.5f : en) : (en > 0.f ? -0.5f : en);
}

// ---------------------------------------------------------------------------
// Fused kernel. Blocks [0,640): pool+argmax (batch-major). Blocks [640,1920):
// attn. Pass 2 re-reads ENERGY (L1/L2-resident) and recomputes the edit so
// pass-2 loads do NOT depend on pass-1 stores (no RAW-through-L2 stall);
// eout/aout stores are pure streaming.
// ---------------------------------------------------------------------------
__global__ __launch_bounds__(256) void fused_kernel(const float* __restrict__ label,
                                                    const float* __restrict__ energy,
                                                    float* __restrict__ out)
{
    const int bid = blockIdx.x;
    const int t   = threadIdx.x;

    __shared__ int lab_s[P];

    if (bid < POOL_BLOCKS) {
        // ================= POOL + ARGMAX =================
        const int b   = bid / POOL_PER_B;
        const int rem = bid % POOL_PER_B;
        const int hh  = rem / NWCH;
        const int wc  = rem % NWCH;
        const int f   = t & 63;
        const int cg  = t >> 6;

        float (*ssum)[17] = reinterpret_cast<float(*)[17]>(lab_s);

        const int h0 = (HH_OFF + hh) * 16;
        const int row_f4 = W / 4;

#pragma unroll
        for (int c4 = 0; c4 < 5; c4++) {
            const int c = c4 * 4 + cg;
            float acc = 0.f;
            if (c < C) {
                const float4* p = reinterpret_cast<const float4*>(
                    label + (((size_t)b * C + c) * H + h0) * W + wc * WCHUNK) + f;
#pragma unroll
                for (int r = 0; r < 16; r++) {
                    float4 v = __ldcs(p + (size_t)r * row_f4);
                    acc += (v.x + v.y) + (v.z + v.w);
                }
            }
            acc += __shfl_xor_sync(0xffffffffu, acc, 1);
            acc += __shfl_xor_sync(0xffffffffu, acc, 2);
            if (c < C && (t & 3) == 0) ssum[c][f >> 2] = acc;
        }
        __syncthreads();

        if (t < 16) {
            float best = ssum[0][t];
            int bi = 0;
#pragma unroll
            for (int c = 1; c < C; c++) {
                float v = ssum[c][t];
                if (v > best) { best = v; bi = c; }   // strict '>' = first-max
            }
            g_lab[(b * HH_N + hh) * WW + wc * 16 + t] = bi;
        }
        __syncthreads();
        __threadfence();
        if (t == 0) atomicAdd(&g_done[b], 1);
    } else {
        // ================= ATTN (two-pass, warp-per-row) =================
        const int aid = bid - POOL_BLOCKS;
        const int b   = aid / ATTN_PER_B;
        const int i0  = (aid % ATTN_PER_B) * RWARPS;
        const int wid = t >> 5;
        const int lid = t & 31;

        // Prefetch energy slice into L2 (minor win during pool's final drain).
        {
            const char* base = reinterpret_cast<const char*>(
                energy + ((size_t)b * P + i0) * P);
            prefetch_l2(base + (size_t)t * 128);
            if (t < SLICE_LINES - 256)
                prefetch_l2(base + (size_t)(t + 256) * 128);
        }

        if (t == 0) {
            while (ld_relaxed_gpu(&g_done[b]) < POOL_PER_B) __nanosleep(500);
        }
        __syncthreads();
        __threadfence();

        reinterpret_cast<int4*>(lab_s)[t] =
            reinterpret_cast<const int4*>(g_lab + b * P)[t];
        if (t < 64)
            reinterpret_cast<int4*>(lab_s)[256 + t] =
                reinterpret_cast<const int4*>(g_lab + b * P)[256 + t];
        __syncthreads();

        const int i  = i0 + wid;
        const int li = lab_s[i];

        const float4* erow = reinterpret_cast<const float4*>(
            energy + ((size_t)b * P + i) * P);
        float4* eout = reinterpret_cast<float4*>(out + ((size_t)b * P + i) * P);
        float4* aout = reinterpret_cast<float4*>(out + NE + ((size_t)b * P + i) * P);
        const int4* lab4 = reinterpret_cast<const int4*>(lab_s);

        // Pass 1: mask-edit, STREAM ev -> eout (never re-read), accumulate
        // exp-sum with 4 partial accumulators. Default loads: energy must
        // stay L1/L2-resident for pass 2. No max-shift (values bounded,
        // f32 exp safe, softmax shift-invariant).
        float s0 = 0.f, s1 = 0.f, s2 = 0.f, s3 = 0.f;
#pragma unroll
        for (int k = 0; k < CH; k++) {
            const int j = lid + k * 32;
            float4 en = erow[j];
            int4  lj = lab4[j];

            float4 ev;
            ev.x = edit1(en.x, lj.x == li);
            ev.y = edit1(en.y, lj.y == li);
            ev.z = edit1(en.z, lj.z == li);
            ev.w = edit1(en.w, lj.w == li);

            __stcs(eout + j, ev);

            s0 += __expf(ev.x);
            s1 += __expf(ev.y);
            s2 += __expf(ev.z);
            s3 += __expf(ev.w);
        }
        float s = (s0 + s1) + (s2 + s3);

#pragma unroll
        for (int o = 16; o > 0; o >>= 1) s += __shfl_xor_sync(0xffffffffu, s, o);
        const float inv = 1.f / s;

        // Pass 2: re-read ENERGY (L1/L2 hit, independent of pass-1 stores),
        // recompute edit + exp, scale, stream to aout.
#pragma unroll
        for (int k = 0; k < CH; k++) {
            const int j = lid + k * 32;
            float4 en = erow[j];
            int4  lj = lab4[j];

            float4 am;
            am.x = __expf(edit1(en.x, lj.x == li)) * inv;
            am.y = __expf(edit1(en.y, lj.y == li)) * inv;
            am.z = __expf(edit1(en.z, lj.z == li)) * inv;
            am.w = __expf(edit1(en.w, lj.w == li)) * inv;
            __stcs(aout + j, am);
        }

        // Self-reset for next graph replay.
        if (t == 0) {
            int old = atomicAdd(&g_cons[b], 1);
            if (old == ATTN_PER_B - 1) {
                g_done[b] = 0;
                g_cons[b] = 0;
            }
        }
    }
}

extern "C" void kernel_launch(void* const* d_in, const int* in_sizes, int n_in,
                              void* d_out, int out_size)
{
    const float* label  = (const float*)d_in[0];  // [8,19,320,2048] f32
    const float* energy = (const float*)d_in[1];  // [8,1280,1280]  f32
    float* out = (float*)d_out;                   // e then attention_map

    (void)in_sizes; (void)n_in; (void)out_size;

    fused_kernel<<<POOL_BLOCKS + ATTN_BLOCKS, 256>>>(label, energy, out);
}

// round 12
// speedup vs baseline: 1.0135x; 1.0135x over previous
#include <cuda_runtime.h>
#include <cstdint>

// Problem constants
constexpr int B  = 8;
constexpr int C  = 19;
constexpr int H  = 320;
constexpr int W  = 2048;
constexpr int HH_OFF = 10;
constexpr int HH_N  = 10;
constexpr int WW   = 128;
constexpr int P    = HH_N * WW;      // 1280
constexpr long long NE = (long long)B * P * P;

constexpr int WCHUNK = 256;
constexpr int NWCH   = W / WCHUNK;       // 8
constexpr int POOL_PER_B = HH_N * NWCH;  // 80
constexpr int POOL_BLOCKS = B * POOL_PER_B;   // 640
constexpr int RWARPS = 8;
constexpr int ATTN_PER_B = P / RWARPS;   // 160
constexpr int ATTN_BLOCKS = B * ATTN_PER_B;   // 1280
constexpr int CH = P / 4 / 32;           // 10

constexpr int ROW_BYTES   = P * 4;
constexpr int SLICE_BYTES = RWARPS * ROW_BYTES;  // 40960
constexpr int SLICE_LINES = SLICE_BYTES / 128;   // 320

__device__ int g_lab[B * P];
__device__ int g_done[B];
__device__ int g_cons[B];

__device__ __forceinline__ int ld_relaxed_gpu(const int* p) {
    int v;
    asm volatile("ld.global.relaxed.gpu.b32 %0, [%1];" : "=r"(v) : "l"(p));
    return v;
}

__device__ __forceinline__ void prefetch_l2(const void* p) {
    asm volatile("prefetch.global.L2 [%0];" :: "l"(p));
}

// ---------------------------------------------------------------------------
// Fused kernel. Blocks [0,640): pool+argmax (batch-major). Blocks [640,1920):
// attn with ROUND-ROBIN batch mapping: wave-1 resident attn blocks cover all
// 8 batches, so every batch's attn (and its L2 energy prefetch) starts as
// early as possible; post-pool tail is nearly pure write drain.
// ---------------------------------------------------------------------------
__global__ __launch_bounds__(256) void fused_kernel(const float* __restrict__ label,
                                                    const float* __restrict__ energy,
                                                    float* __restrict__ out)
{
    const int bid = blockIdx.x;
    const int t   = threadIdx.x;

    __shared__ int lab_s[P];

    if (bid < POOL_BLOCKS) {
        // ================= POOL + ARGMAX =================
        const int b   = bid / POOL_PER_B;
        const int rem = bid % POOL_PER_B;
        const int hh  = rem / NWCH;
        const int wc  = rem % NWCH;
        const int f   = t & 63;
        const int cg  = t >> 6;

        float (*ssum)[17] = reinterpret_cast<float(*)[17]>(lab_s);

        const int h0 = (HH_OFF + hh) * 16;
        const int row_f4 = W / 4;

#pragma unroll
        for (int c4 = 0; c4 < 5; c4++) {
            const int c = c4 * 4 + cg;
            float acc = 0.f;
            if (c < C) {
                const float4* p = reinterpret_cast<const float4*>(
                    label + (((size_t)b * C + c) * H + h0) * W + wc * WCHUNK) + f;
#pragma unroll
                for (int r = 0; r < 16; r++) {
                    float4 v = __ldcs(p + (size_t)r * row_f4);
                    acc += (v.x + v.y) + (v.z + v.w);
                }
            }
            acc += __shfl_xor_sync(0xffffffffu, acc, 1);
            acc += __shfl_xor_sync(0xffffffffu, acc, 2);
            if (c < C && (t & 3) == 0) ssum[c][f >> 2] = acc;
        }
        __syncthreads();

        if (t < 16) {
            float best = ssum[0][t];
            int bi = 0;
#pragma unroll
            for (int c = 1; c < C; c++) {
                float v = ssum[c][t];
                if (v > best) { best = v; bi = c; }   // strict '>' = first-max
            }
            g_lab[(b * HH_N + hh) * WW + wc * 16 + t] = bi;
        }
        __syncthreads();
        __threadfence();
        if (t == 0) atomicAdd(&g_done[b], 1);
    } else {
        // ================= ATTN (two-pass, warp-per-row) =================
        const int aid = bid - POOL_BLOCKS;
        const int b   = aid % B;                    // round-robin batches
        const int i0  = (aid / B) * RWARPS;
        const int wid = t >> 5;
        const int lid = t & 31;

        // Prefetch this block's 40KB energy slice into L2 before polling.
        {
            const char* base = reinterpret_cast<const char*>(
                energy + ((size_t)b * P + i0) * P);
            prefetch_l2(base + (size_t)t * 128);
            if (t < SLICE_LINES - 256)
                prefetch_l2(base + (size_t)(t + 256) * 128);
        }

        if (t == 0) {
            while (ld_relaxed_gpu(&g_done[b]) < POOL_PER_B) __nanosleep(256);
        }
        __syncthreads();
        __threadfence();

        reinterpret_cast<int4*>(lab_s)[t] =
            reinterpret_cast<const int4*>(g_lab + b * P)[t];
        if (t < 64)
            reinterpret_cast<int4*>(lab_s)[256 + t] =
                reinterpret_cast<const int4*>(g_lab + b * P)[256 + t];
        __syncthreads();

        const int i  = i0 + wid;
        const int li = lab_s[i];

        const float4* erow = reinterpret_cast<const float4*>(
            energy + ((size_t)b * P + i) * P);
        float4* eout = reinterpret_cast<float4*>(out + ((size_t)b * P + i) * P);
        float4* aout = reinterpret_cast<float4*>(out + NE + ((size_t)b * P + i) * P);
        const int4* lab4 = reinterpret_cast<const int4*>(lab_s);

        // Pass 1: mask-edit, store e (regular store, L2-resident for pass 2),
        // accumulate exp-sum. No max-shift (values bounded ~|7|, f32 exp safe,
        // softmax shift-invariant).
        float s = 0.f;
#pragma unroll
        for (int k = 0; k < CH; k++) {
            const int j = lid + k * 32;
            float4 en = erow[j];
            int4  lj = lab4[j];

            float4 ev;
            ev.x = (lj.x == li) ? (en.x < 0.f ? 0.5f : en.x) : (en.x > 0.f ? -0.5f : en.x);
            ev.y = (lj.y == li) ? (en.y < 0.f ? 0.5f : en.y) : (en.y > 0.f ? -0.5f : en.y);
            ev.z = (lj.z == li) ? (en.z < 0.f ? 0.5f : en.z) : (en.z > 0.f ? -0.5f : en.z);
            ev.w = (lj.w == li) ? (en.w < 0.f ? 0.5f : en.w) : (en.w > 0.f ? -0.5f : en.w);

            eout[j] = ev;   // re-read in pass 2 (L2 hit)

            s += (__expf(ev.x) + __expf(ev.y)) + (__expf(ev.z) + __expf(ev.w));
        }

#pragma unroll
        for (int o = 16; o > 0; o >>= 1) s += __shfl_xor_sync(0xffffffffu, s, o);
        const float inv = 1.f / s;

        // Pass 2: reload ev from L2, recompute exp, single streaming store.
#pragma unroll
        for (int k = 0; k < CH; k++) {
            const int j = lid + k * 32;
            float4 ev = eout[j];
            float4 am;
            am.x = __expf(ev.x) * inv;
            am.y = __expf(ev.y) * inv;
            am.z = __expf(ev.z) * inv;
            am.w = __expf(ev.w) * inv;
            __stcs(aout + j, am);
        }

        // Self-reset for next graph replay.
        if (t == 0) {
            int old = atomicAdd(&g_cons[b], 1);
            if (old == ATTN_PER_B - 1) {
                g_done[b] = 0;
                g_cons[b] = 0;
            }
        }
    }
}

extern "C" void kernel_launch(void* const* d_in, const int* in_sizes, int n_in,
                              void* d_out, int out_size)
{
    const float* label  = (const float*)d_in[0];  // [8,19,320,2048] f32
    const float* energy = (const float*)d_in[1];  // [8,1280,1280]  f32
    float* out = (float*)d_out;                   // e then attention_map

    (void)in_sizes; (void)n_in; (void)out_size;

    fused_kernel<<<POOL_BLOCKS + ATTN_BLOCKS, 256>>>(label, energy, out);
}